// round 5
// baseline (speedup 1.0000x reference)
#include <cuda_runtime.h>
#include <math.h>
#include <stdint.h>

#define B_ 2
#define N_ 4096
#define M_ 4096
#define D_ 512
#define H_ 8
#define P_ 64

// Q is pre-scaled by 0.125 * log2(e) so attention softmax can use exp2f directly.
#define QSCALE 0.18033688011112042f

// Scratch (all values tf32-pre-rounded by proj_kernel):
// g_Q: [b,h,n,p]  with p permuted per 8-group {0,4,1,5,2,6,3,7}
// g_K: [b,h,m,p]  with p permuted likewise
// g_V: [b,h,p,m]  TRANSPOSED, with m permuted per 8-group likewise
__device__ float g_Q[(size_t)B_ * H_ * N_ * P_];
__device__ float g_K[(size_t)B_ * H_ * M_ * P_];
__device__ float g_V[(size_t)B_ * H_ * P_ * M_];

__device__ __forceinline__ float tf32r(float x) {
    uint32_t r;
    asm("cvt.rna.tf32.f32 %0, %1;" : "=r"(r) : "f"(x));
    return __uint_as_float(r);
}

__device__ __forceinline__ void mma8(float* c, const float* a, float b0, float b1) {
    asm volatile(
        "mma.sync.aligned.m16n8k8.row.col.f32.tf32.tf32.f32 "
        "{%0,%1,%2,%3}, {%4,%5,%6,%7}, {%8,%9}, {%0,%1,%2,%3};"
        : "+f"(c[0]), "+f"(c[1]), "+f"(c[2]), "+f"(c[3])
        : "r"(__float_as_uint(a[0])), "r"(__float_as_uint(a[1])),
          "r"(__float_as_uint(a[2])), "r"(__float_as_uint(a[3])),
          "r"(__float_as_uint(b0)), "r"(__float_as_uint(b1)));
}

__device__ __forceinline__ void cp16(uint32_t dst, const void* src) {
    asm volatile("cp.async.cg.shared.global [%0], [%1], 16;\n" :: "r"(dst), "l"(src));
}
__device__ __forceinline__ void cp_commit() {
    asm volatile("cp.async.commit_group;\n" ::: "memory");
}
template <int NN>
__device__ __forceinline__ void cp_wait() {
    asm volatile("cp.async.wait_group %0;\n" :: "n"(NN) : "memory");
}

// ---------------------------------------------------------------------------
// Projection GEMM (tf32 MMA). Epilogue: tf32-round, permute, (transpose for V),
// pre-scale Q by QSCALE.
// ---------------------------------------------------------------------------
__global__ __launch_bounds__(256) void proj_kernel(
    const float* __restrict__ xq, const float* __restrict__ xk, const float* __restrict__ xv,
    const float* __restrict__ Wq, const float* __restrict__ Wk, const float* __restrict__ Wv,
    const float* __restrict__ bq, const float* __restrict__ bk, const float* __restrict__ bv)
{
    const float* X; const float* W; const float* bias;
    if (blockIdx.z == 0)      { X = xq; W = Wq; bias = bq; }
    else if (blockIdx.z == 1) { X = xk; W = Wk; bias = bk; }
    else                      { X = xv; W = Wv; bias = bv; }

    __shared__ float Xs[128 * 36];
    __shared__ float Ws[32 * 72];

    const int tid = threadIdx.x;
    const int w = tid >> 5, lane = tid & 31;
    const int g = lane >> 2, t = lane & 3;
    const int r0 = blockIdx.y * 128;
    const int c0 = blockIdx.x * 64;

    float c[8][4];
    #pragma unroll
    for (int j = 0; j < 8; j++)
        #pragma unroll
        for (int e = 0; e < 4; e++) c[j][e] = 0.f;

    for (int k0 = 0; k0 < D_; k0 += 32) {
        __syncthreads();
        #pragma unroll
        for (int i = 0; i < 4; i++) {
            int fi = i * 256 + tid;
            int row = fi >> 3, cg = fi & 7;
            float4 v = *(const float4*)&X[(r0 + row) * D_ + k0 + cg * 4];
            *(float4*)&Xs[row * 36 + cg * 4] =
                make_float4(tf32r(v.x), tf32r(v.y), tf32r(v.z), tf32r(v.w));
        }
        #pragma unroll
        for (int i = 0; i < 2; i++) {
            int fi = i * 256 + tid;
            int row = fi >> 4, cg = fi & 15;
            float4 v = *(const float4*)&W[(k0 + row) * D_ + c0 + cg * 4];
            *(float4*)&Ws[row * 72 + cg * 4] =
                make_float4(tf32r(v.x), tf32r(v.y), tf32r(v.z), tf32r(v.w));
        }
        __syncthreads();

        #pragma unroll
        for (int kk = 0; kk < 4; kk++) {
            float a[4];
            a[0] = Xs[(w * 16 + g)     * 36 + kk * 8 + t];
            a[1] = Xs[(w * 16 + g + 8) * 36 + kk * 8 + t];
            a[2] = Xs[(w * 16 + g)     * 36 + kk * 8 + t + 4];
            a[3] = Xs[(w * 16 + g + 8) * 36 + kk * 8 + t + 4];
            #pragma unroll
            for (int j = 0; j < 8; j++) {
                float b0 = Ws[(kk * 8 + t)     * 72 + j * 8 + g];
                float b1 = Ws[(kk * 8 + t + 4) * 72 + j * 8 + g];
                mma8(c[j], a, b0, b1);
            }
        }
    }

    const int h = blockIdx.x;
    // permuted positions for C-frag cols 2t (pp0) and 2t+1 (pp1)
    const int pp0 = (t < 2) ? 4 * t     : 4 * t - 7;
    const int pp1 = (t < 2) ? 4 * t + 2 : 4 * t - 5;

    if (blockIdx.z < 2) {
        float* out = (blockIdx.z == 0) ? g_Q : g_K;
        const float scale = (blockIdx.z == 0) ? QSCALE : 1.0f;
        #pragma unroll
        for (int j = 0; j < 8; j++) {
            int oc = j * 8 + 2 * t;
            float b0v = bias[c0 + oc], b1v = bias[c0 + oc + 1];
            int r = r0 + w * 16 + g;
            int bi = r >> 12, n = r & (N_ - 1);
            float* dst = out + (((size_t)(bi * H_ + h) * N_) + n) * P_;
            dst[j * 8 + pp0] = tf32r((c[j][0] + b0v) * scale);
            dst[j * 8 + pp1] = tf32r((c[j][1] + b1v) * scale);
            r += 8; bi = r >> 12; n = r & (N_ - 1);
            float* dst2 = out + (((size_t)(bi * H_ + h) * N_) + n) * P_;
            dst2[j * 8 + pp0] = tf32r((c[j][2] + b0v) * scale);
            dst2[j * 8 + pp1] = tf32r((c[j][3] + b1v) * scale);
        }
    } else {
        // V: store transposed [b,h][p][perm(m)]
        const int gp = (g < 4) ? 2 * g : 2 * (g - 4) + 1;   // perm of m within 8-group
        #pragma unroll
        for (int j = 0; j < 8; j++) {
            #pragma unroll
            for (int e = 0; e < 2; e++) {
                int oc = j * 8 + 2 * t + e;
                float bv_ = bias[c0 + oc];
                int r = r0 + w * 16 + g;
                int bi = r >> 12, m = r & (M_ - 1);
                size_t base = ((size_t)(bi * H_ + h) * P_ + oc) * M_;
                g_V[base + (size_t)((m & ~7) | gp)] = tf32r(c[j][e] + bv_);
                r += 8; bi = r >> 12; m = r & (M_ - 1);
                size_t base2 = ((size_t)(bi * H_ + h) * P_ + oc) * M_;
                g_V[base2 + (size_t)((m & ~7) | gp)] = tf32r(c[j][e + 2] + bv_);
            }
        }
    }
}

// ---------------------------------------------------------------------------
// Flash attention: CTA = (b, h, 128 q-rows), 8 warps (warp = 16 rows).
// Q in registers (reused over all tiles). cp.async double-buffered K/V.
// Ps aliases the Q staging buffer. All operands pre-rounded tf32.
// smem: Ps/Qs [128*68] | Ks[2][64*68] | Vs[2][64*68] = 104448 B.
// ---------------------------------------------------------------------------
#define KBUF (64 * 68)

__global__ __launch_bounds__(256, 2) void attn_kernel(float* __restrict__ out)
{
    extern __shared__ float smem[];
    float* Ps = smem;                   // [128][68]  (Q staged here first)
    float* Ks = smem + 128 * 68;        // [2][64][68]
    float* Vs = Ks + 2 * KBUF;          // [2][64][68]  (rows = p, cols = perm kv)

    const int tid = threadIdx.x;
    const int w = tid >> 5, lane = tid & 31;
    const int g = lane >> 2, t = lane & 3;
    const int b = blockIdx.z, h = blockIdx.y;
    const int n0 = blockIdx.x * 128;
    const int qrow = w * 16;

    const float* Qg = g_Q + ((size_t)(b * H_ + h) * N_ + n0) * P_;
    const float* Kg = g_K + (size_t)(b * H_ + h) * M_ * P_;
    const float* Vg = g_V + (size_t)(b * H_ + h) * P_ * M_;   // [p][perm m]

    uint32_t ps_a = (uint32_t)__cvta_generic_to_shared(Ps);
    uint32_t ks_a = (uint32_t)__cvta_generic_to_shared(Ks);
    uint32_t vs_a = (uint32_t)__cvta_generic_to_shared(Vs);

    const int srow = tid >> 4, scg = tid & 15;   // staging mapping (K/V: 4 iters)

    // ---- prologue: G0 = Q + tile0, G1 = tile1 ----
    #pragma unroll
    for (int i = 0; i < 8; i++) {        // Q: 128 rows x 16 chunks
        int idx = i * 256 + tid;
        int row = idx >> 4, cg = idx & 15;
        cp16(ps_a + (row * 68 + cg * 4) * 4, Qg + row * P_ + cg * 4);
    }
    #pragma unroll
    for (int i = 0; i < 4; i++) {        // K0 + V0
        int row = i * 16 + srow;
        cp16(ks_a + (row * 68 + scg * 4) * 4, Kg + (size_t)row * P_ + scg * 4);
        cp16(vs_a + (row * 68 + scg * 4) * 4, Vg + (size_t)row * M_ + scg * 4);
    }
    cp_commit();
    #pragma unroll
    for (int i = 0; i < 4; i++) {        // K1 + V1 into buf 1
        int row = i * 16 + srow;
        cp16(ks_a + (KBUF + row * 68 + scg * 4) * 4, Kg + (size_t)(64 + row) * P_ + scg * 4);
        cp16(vs_a + (KBUF + row * 68 + scg * 4) * 4, Vg + (size_t)row * M_ + 64 + scg * 4);
    }
    cp_commit();

    cp_wait<1>();
    __syncthreads();

    // ---- extract Q fragments to registers (own warp rows only) ----
    float q[8][4];
    #pragma unroll
    for (int kk = 0; kk < 8; kk++) {
        float2 v0 = *(float2*)&Ps[(qrow + g)     * 68 + kk * 8 + t * 2];
        float2 v1 = *(float2*)&Ps[(qrow + g + 8) * 68 + kk * 8 + t * 2];
        q[kk][0] = v0.x; q[kk][2] = v0.y;
        q[kk][1] = v1.x; q[kk][3] = v1.y;
    }

    float m0 = -INFINITY, m1 = -INFINITY, l0 = 0.f, l1 = 0.f;
    float o[8][4];
    #pragma unroll
    for (int j = 0; j < 8; j++)
        #pragma unroll
        for (int e = 0; e < 4; e++) o[j][e] = 0.f;

    for (int tile = 0; tile < M_ / 64; tile++) {
        const int buf = tile & 1;
        float* Kb = Ks + buf * KBUF;
        float* Vb = Vs + buf * KBUF;

        if (tile > 0) {
            if (tile < 63) cp_wait<1>(); else cp_wait<0>();
            __syncthreads();
        }

        // ---- S = Q @ K^T ----
        float s[8][4];
        #pragma unroll
        for (int j = 0; j < 8; j++)
            #pragma unroll
            for (int e = 0; e < 4; e++) s[j][e] = 0.f;

        #pragma unroll
        for (int kk = 0; kk < 8; kk++) {
            #pragma unroll
            for (int j = 0; j < 8; j++) {
                float2 b2 = *(float2*)&Kb[(j * 8 + g) * 68 + kk * 8 + t * 2];
                mma8(s[j], q[kk], b2.x, b2.y);
            }
        }

        // ---- online softmax (base-2; scale folded into Q) ----
        float rmax0 = -INFINITY, rmax1 = -INFINITY;
        #pragma unroll
        for (int j = 0; j < 8; j++) {
            rmax0 = fmaxf(rmax0, fmaxf(s[j][0], s[j][1]));
            rmax1 = fmaxf(rmax1, fmaxf(s[j][2], s[j][3]));
        }
        #pragma unroll
        for (int off = 1; off <= 2; off <<= 1) {
            rmax0 = fmaxf(rmax0, __shfl_xor_sync(0xffffffffu, rmax0, off));
            rmax1 = fmaxf(rmax1, __shfl_xor_sync(0xffffffffu, rmax1, off));
        }
        float mn0 = fmaxf(m0, rmax0), mn1 = fmaxf(m1, rmax1);
        float alpha0 = exp2f(m0 - mn0), alpha1 = exp2f(m1 - mn1);
        m0 = mn0; m1 = mn1;

        float rs0 = 0.f, rs1 = 0.f;
        #pragma unroll
        for (int j = 0; j < 8; j++) {
            s[j][0] = exp2f(s[j][0] - m0); rs0 += s[j][0];
            s[j][1] = exp2f(s[j][1] - m0); rs0 += s[j][1];
            s[j][2] = exp2f(s[j][2] - m1); rs1 += s[j][2];
            s[j][3] = exp2f(s[j][3] - m1); rs1 += s[j][3];
        }
        #pragma unroll
        for (int off = 1; off <= 2; off <<= 1) {
            rs0 += __shfl_xor_sync(0xffffffffu, rs0, off);
            rs1 += __shfl_xor_sync(0xffffffffu, rs1, off);
        }
        l0 = l0 * alpha0 + rs0;
        l1 = l1 * alpha1 + rs1;
        #pragma unroll
        for (int j = 0; j < 8; j++) {
            o[j][0] *= alpha0; o[j][1] *= alpha0;
            o[j][2] *= alpha1; o[j][3] *= alpha1;
        }

        // ---- stage P (warp-private rows; no CTA barrier needed) ----
        __syncwarp();
        #pragma unroll
        for (int j = 0; j < 8; j++) {
            *(float2*)&Ps[(qrow + g)     * 68 + j * 8 + t * 2] =
                make_float2(tf32r(s[j][0]), tf32r(s[j][1]));
            *(float2*)&Ps[(qrow + g + 8) * 68 + j * 8 + t * 2] =
                make_float2(tf32r(s[j][2]), tf32r(s[j][3]));
        }
        __syncwarp();

        // ---- O += P @ V ----
        #pragma unroll
        for (int kk = 0; kk < 8; kk++) {
            float a4[4];
            a4[0] = Ps[(qrow + g)     * 68 + kk * 8 + t];
            a4[2] = Ps[(qrow + g)     * 68 + kk * 8 + t + 4];
            a4[1] = Ps[(qrow + g + 8) * 68 + kk * 8 + t];
            a4[3] = Ps[(qrow + g + 8) * 68 + kk * 8 + t + 4];
            #pragma unroll
            for (int j = 0; j < 8; j++) {
                float2 b2 = *(float2*)&Vb[(j * 8 + g) * 68 + kk * 8 + t * 2];
                mma8(o[j], a4, b2.x, b2.y);
            }
        }

        __syncthreads();   // all warps done with Kb/Vb before refill

        if (tile + 2 < M_ / 64) {
            const float* Kt = Kg + (size_t)(tile + 2) * 64 * P_;
            const float* Vt = Vg + (size_t)(tile + 2) * 64;
            #pragma unroll
            for (int i = 0; i < 4; i++) {
                int row = i * 16 + srow;
                cp16(ks_a + (buf * KBUF + row * 68 + scg * 4) * 4,
                     Kt + (size_t)row * P_ + scg * 4);
                cp16(vs_a + (buf * KBUF + row * 68 + scg * 4) * 4,
                     Vt + (size_t)row * M_ + scg * 4);
            }
            cp_commit();
        }
    }

    // ---- epilogue ----
    float inv0 = 1.f / l0, inv1 = 1.f / l1;
    #pragma unroll
    for (int j = 0; j < 8; j++) {
        int pcol = j * 8 + t * 2;
        int n = n0 + qrow + g;
        *(float2*)&out[(size_t)(b * N_ + n) * D_ + h * 64 + pcol] =
            make_float2(o[j][0] * inv0, o[j][1] * inv0);
        n += 8;
        *(float2*)&out[(size_t)(b * N_ + n) * D_ + h * 64 + pcol] =
            make_float2(o[j][2] * inv1, o[j][3] * inv1);
    }
}

// ---------------------------------------------------------------------------
extern "C" void kernel_launch(void* const* d_in, const int* in_sizes, int n_in,
                              void* d_out, int out_size)
{
    const float* xq = (const float*)d_in[0];
    const float* xk = (const float*)d_in[1];
    const float* xv = (const float*)d_in[2];
    const float* Wq = (const float*)d_in[3];
    const float* bq = (const float*)d_in[4];
    const float* Wk = (const float*)d_in[5];
    const float* bk = (const float*)d_in[6];
    const float* Wv = (const float*)d_in[7];
    const float* bv = (const float*)d_in[8];
    float* out = (float*)d_out;

    const int attn_smem = (128 * 68 + 4 * KBUF) * (int)sizeof(float);  // 104448
    cudaFuncSetAttribute(attn_kernel, cudaFuncAttributeMaxDynamicSharedMemorySize, attn_smem);

    proj_kernel<<<dim3(D_ / 64, (B_ * N_) / 128, 3), 256>>>(xq, xk, xv, Wq, Wk, Wv, bq, bk, bv);
    attn_kernel<<<dim3(N_ / 128, H_, B_), 256, attn_smem>>>(out);
}